// round 1
// baseline (speedup 1.0000x reference)
#include <cuda_runtime.h>
#include <math.h>

#define BATCH 2
#define TSEQ  2048
#define CDIM  1024
#define NHEAD 16
#define HDIM  64
#define MROWS (BATCH*TSEQ)          // 4096
#define QKV_N (3*CDIM)              // 3072

// Scratch: device globals (no runtime allocation allowed)
__device__ float g_qkv[MROWS * QKV_N];   // [B*T, 3C]  (Q|K|V interleaved per row)
__device__ float g_y  [MROWS * CDIM];    // [B*T, C]   attention output

// ---------------------------------------------------------------------------
// SGEMM: C[M,N] = A[M,K] @ B[K,N] + bias[N]
// 128x128 tile, BK=8, 256 threads, 8x8 per-thread microtile.
// All problem dims here are multiples of the tile sizes (no bounds checks).
// ---------------------------------------------------------------------------
__global__ __launch_bounds__(256) void sgemm_bias(
    const float* __restrict__ A, const float* __restrict__ B,
    const float* __restrict__ bias, float* __restrict__ C,
    int M, int N, int K)
{
    __shared__ float As[8][128];
    __shared__ float Bs[8][128];

    const int tid  = threadIdx.x;
    const int row0 = blockIdx.y * 128;
    const int col0 = blockIdx.x * 128;
    const int ty   = tid >> 4;          // 0..15
    const int tx   = tid & 15;          // 0..15

    const int a_r = tid >> 1;           // 0..127
    const int a_c = (tid & 1) * 4;      // 0 or 4
    const int b_r = tid >> 5;           // 0..7
    const int b_c = (tid & 31) * 4;     // 0..124

    float acc[8][8];
    #pragma unroll
    for (int i = 0; i < 8; ++i)
        #pragma unroll
        for (int j = 0; j < 8; ++j) acc[i][j] = 0.f;

    const float* Ab = A + (row0 + a_r) * K + a_c;
    const float* Bb = B + b_r * N + col0 + b_c;

    for (int kt = 0; kt < K; kt += 8) {
        float4 a4 = *(const float4*)(Ab + kt);
        float4 b4 = *(const float4*)(Bb + kt * N);
        As[a_c + 0][a_r] = a4.x;
        As[a_c + 1][a_r] = a4.y;
        As[a_c + 2][a_r] = a4.z;
        As[a_c + 3][a_r] = a4.w;
        *(float4*)&Bs[b_r][b_c] = b4;
        __syncthreads();

        #pragma unroll
        for (int k = 0; k < 8; ++k) {
            float4 a0 = *(const float4*)&As[k][ty * 8];
            float4 a1 = *(const float4*)&As[k][ty * 8 + 4];
            float4 b0 = *(const float4*)&Bs[k][tx * 8];
            float4 b1 = *(const float4*)&Bs[k][tx * 8 + 4];
            float ar[8] = {a0.x, a0.y, a0.z, a0.w, a1.x, a1.y, a1.z, a1.w};
            float br[8] = {b0.x, b0.y, b0.z, b0.w, b1.x, b1.y, b1.z, b1.w};
            #pragma unroll
            for (int i = 0; i < 8; ++i)
                #pragma unroll
                for (int j = 0; j < 8; ++j)
                    acc[i][j] += ar[i] * br[j];
        }
        __syncthreads();
    }

    #pragma unroll
    for (int i = 0; i < 8; ++i) {
        int row = row0 + ty * 8 + i;
        #pragma unroll
        for (int j4 = 0; j4 < 2; ++j4) {
            int col = col0 + tx * 8 + j4 * 4;
            float4 bv = *(const float4*)&bias[col];
            float4 o;
            o.x = acc[i][j4 * 4 + 0] + bv.x;
            o.y = acc[i][j4 * 4 + 1] + bv.y;
            o.z = acc[i][j4 * 4 + 2] + bv.z;
            o.w = acc[i][j4 * 4 + 3] + bv.w;
            *(float4*)&C[row * N + col] = o;
        }
    }
}

// ---------------------------------------------------------------------------
// Flash attention (causal), fp32.
// Block: 64 queries x one head. 128 threads: 2 threads per query row,
// each owning half the key-tile columns (16 of 32) and half the output dims
// (32 of 64). KV tiles of 32 keys.
// grid = (T/64, H, B)
// ---------------------------------------------------------------------------
__global__ __launch_bounds__(128) void flash_attn(
    const float* __restrict__ qkv, float* __restrict__ y)
{
    __shared__ float Qs[64][68];
    __shared__ float Ks[32][68];
    __shared__ float Vs[32][68];
    __shared__ float Ps[64][36];

    const int tid = threadIdx.x;
    const int q0  = blockIdx.x * 64;
    const int h   = blockIdx.y;
    const int b   = blockIdx.z;
    const int r   = tid >> 1;     // query row within tile (0..63)
    const int hh  = tid & 1;      // half index

    const size_t base = (size_t)b * TSEQ * QKV_N + h * HDIM;

    // Load Q tile (64 x 64)
    for (int i = tid; i < 64 * 16; i += 128) {
        int row = i >> 4;
        int c4  = (i & 15) * 4;
        *(float4*)&Qs[row][c4] =
            *(const float4*)&qkv[base + (size_t)(q0 + row) * QKV_N + c4];
    }

    float m = -INFINITY, l = 0.f;
    float acc[32];
    #pragma unroll
    for (int i = 0; i < 32; ++i) acc[i] = 0.f;

    const int q = q0 + r;                 // this thread's global query index
    const int ntiles = (q0 + 64) / 32;
    const float scale = 0.125f;           // 1/sqrt(64)

    for (int t = 0; t < ntiles; ++t) {
        const int j0 = t * 32;
        __syncthreads();   // previous tile's K/V reads complete
        for (int i = tid; i < 32 * 16; i += 128) {
            int row = i >> 4;
            int c4  = (i & 15) * 4;
            size_t rowoff = base + (size_t)(j0 + row) * QKV_N + c4;
            *(float4*)&Ks[row][c4] = *(const float4*)&qkv[rowoff + CDIM];
            *(float4*)&Vs[row][c4] = *(const float4*)&qkv[rowoff + 2 * CDIM];
        }
        __syncthreads();

        // S = Q K^T for this thread's 16 key columns
        float s[16];
        #pragma unroll
        for (int jj = 0; jj < 16; ++jj) s[jj] = 0.f;
        #pragma unroll
        for (int kk4 = 0; kk4 < 16; ++kk4) {
            float4 qv = *(const float4*)&Qs[r][kk4 * 4];
            #pragma unroll
            for (int jj = 0; jj < 16; ++jj) {
                float4 kv = *(const float4*)&Ks[hh * 16 + jj][kk4 * 4];
                s[jj] += qv.x * kv.x + qv.y * kv.y + qv.z * kv.z + qv.w * kv.w;
            }
        }

        if (j0 + 31 > q) {   // diagonal tile: apply causal mask
            #pragma unroll
            for (int jj = 0; jj < 16; ++jj)
                s[jj] = (j0 + hh * 16 + jj <= q) ? s[jj] * scale : -INFINITY;
        } else {
            #pragma unroll
            for (int jj = 0; jj < 16; ++jj) s[jj] *= scale;
        }

        // Online softmax (pair-reduce via shfl)
        float mloc = s[0];
        #pragma unroll
        for (int jj = 1; jj < 16; ++jj) mloc = fmaxf(mloc, s[jj]);
        mloc = fmaxf(mloc, __shfl_xor_sync(0xffffffffu, mloc, 1));
        float mnew = fmaxf(m, mloc);
        float psum = 0.f;
        #pragma unroll
        for (int jj = 0; jj < 16; ++jj) {
            s[jj] = __expf(s[jj] - mnew);
            psum += s[jj];
        }
        psum += __shfl_xor_sync(0xffffffffu, psum, 1);
        float corr = __expf(m - mnew);
        l = l * corr + psum;
        m = mnew;
        #pragma unroll
        for (int i = 0; i < 32; ++i) acc[i] *= corr;

        #pragma unroll
        for (int jj = 0; jj < 16; ++jj) Ps[r][hh * 16 + jj] = s[jj];
        __syncwarp();   // pair exchange (same warp)

        // acc += P @ V over this tile's 32 keys, thread's 32 output dims
        #pragma unroll
        for (int j = 0; j < 32; ++j) {
            float p = Ps[r][j];
            const float4* vrow = (const float4*)&Vs[j][hh * 32];
            #pragma unroll
            for (int d4 = 0; d4 < 8; ++d4) {
                float4 v = vrow[d4];
                acc[d4 * 4 + 0] += p * v.x;
                acc[d4 * 4 + 1] += p * v.y;
                acc[d4 * 4 + 2] += p * v.z;
                acc[d4 * 4 + 3] += p * v.w;
            }
        }
    }

    const float inv = 1.f / l;
    float* yout = &y[((size_t)b * TSEQ + q) * CDIM + h * HDIM + hh * 32];
    #pragma unroll
    for (int d4 = 0; d4 < 8; ++d4) {
        float4 o;
        o.x = acc[d4 * 4 + 0] * inv;
        o.y = acc[d4 * 4 + 1] * inv;
        o.z = acc[d4 * 4 + 2] * inv;
        o.w = acc[d4 * 4 + 3] * inv;
        *(float4*)&yout[d4 * 4] = o;
    }
}

// ---------------------------------------------------------------------------
// Launch: qkv GEMM -> flash attention -> output GEMM
// ---------------------------------------------------------------------------
extern "C" void kernel_launch(void* const* d_in, const int* in_sizes, int n_in,
                              void* d_out, int out_size)
{
    const float* x     = (const float*)d_in[0];
    const float* W_qkv = (const float*)d_in[1];
    const float* b_qkv = (const float*)d_in[2];
    const float* W_o   = (const float*)d_in[3];
    const float* b_o   = (const float*)d_in[4];
    float* out = (float*)d_out;

    float *qkv_ptr, *y_ptr;
    cudaGetSymbolAddress((void**)&qkv_ptr, g_qkv);
    cudaGetSymbolAddress((void**)&y_ptr, g_y);

    // qkv = x @ W_qkv + b_qkv   [4096, 3072]
    sgemm_bias<<<dim3(QKV_N / 128, MROWS / 128), 256>>>(
        x, W_qkv, b_qkv, qkv_ptr, MROWS, QKV_N, CDIM);

    // y = attention(qkv)        [4096, 1024]
    flash_attn<<<dim3(TSEQ / 64, NHEAD, BATCH), 128>>>(qkv_ptr, y_ptr);

    // out = y @ W_o + b_o       [4096, 1024]
    sgemm_bias<<<dim3(CDIM / 128, MROWS / 128), 256>>>(
        y_ptr, W_o, b_o, out, MROWS, CDIM, CDIM);
}

// round 3
// speedup vs baseline: 1.3063x; 1.3063x over previous
#include <cuda_runtime.h>
#include <math.h>
#include <cstdint>

#define BATCH 2
#define TSEQ  2048
#define CDIM  1024
#define NHEAD 16
#define HDIM  64
#define MROWS (BATCH*TSEQ)          // 4096
#define QKV_N (3*CDIM)              // 3072

// Scratch (no runtime allocation allowed)
__device__ float g_qkv[MROWS * QKV_N];     // [B*T, 3C]
__device__ float g_y  [MROWS * CDIM];      // [B*T, C]
__device__ float g_wt_qkv[QKV_N * CDIM];   // W_qkv^T  [3C, C]
__device__ float g_wt_o  [CDIM * CDIM];    // W_o^T    [C, C]

// ---------------------------------------------------------------------------
// helpers
// ---------------------------------------------------------------------------
__device__ __forceinline__ uint32_t smem_u32(const void* p) {
    uint32_t a;
    asm("{ .reg .u64 t; cvta.to.shared.u64 t, %1; cvt.u32.u64 %0, t; }" : "=r"(a) : "l"(p));
    return a;
}
__device__ __forceinline__ uint32_t f2tf(float f) {
    uint32_t u;
    asm("cvt.rna.tf32.f32 %0, %1;" : "=r"(u) : "f"(f));
    return u;
}
#define CP_ASYNC16(dst, src) \
    asm volatile("cp.async.cg.shared.global [%0], [%1], 16;" :: "r"(dst), "l"(src) : "memory")
#define CP_COMMIT() asm volatile("cp.async.commit_group;" ::: "memory")
#define CP_WAIT(n)  asm volatile("cp.async.wait_group %0;" :: "n"(n) : "memory")

__device__ __forceinline__ void mma_tf32(float* c, const uint32_t* a, const uint32_t* b) {
    asm volatile(
        "mma.sync.aligned.m16n8k8.row.col.f32.tf32.tf32.f32 "
        "{%0,%1,%2,%3}, {%4,%5,%6,%7}, {%8,%9}, {%0,%1,%2,%3};"
        : "+f"(c[0]), "+f"(c[1]), "+f"(c[2]), "+f"(c[3])
        : "r"(a[0]), "r"(a[1]), "r"(a[2]), "r"(a[3]), "r"(b[0]), "r"(b[1]));
}

// ---------------------------------------------------------------------------
// mma.sync tf32 GEMM: C[M,N] = A[M,K] @ Bt[N,K]^T + bias[N]
// CTA 128x128, BK=32, 3-stage cp.async. 256 threads = 8 warps (2x4),
// warp tile 64x32 = 4x4 grid of m16n8k8.
// Smem row stride 36 floats (conflict-free fragment loads).
// ---------------------------------------------------------------------------
#define BM 128
#define BN 128
#define BK 32
#define NST 3
#define SROW 36
#define STAGE_FLTS (2 * 128 * SROW)                 // A tile + B tile
#define GEMM_SMEM  (NST * STAGE_FLTS * 4)           // 110592 bytes

__global__ __launch_bounds__(256, 1) void gemm_mma(
    const float* __restrict__ A, const float* __restrict__ Bt,
    const float* __restrict__ bias, float* __restrict__ C,
    int M, int N, int K)
{
    extern __shared__ float sm[];
    const uint32_t sbase = smem_u32(sm);
    const int tid  = threadIdx.x;
    const int lane = tid & 31;
    const int w    = tid >> 5;
    const int wr   = w >> 2;       // 0..1
    const int wc   = w & 3;        // 0..3
    const int row0 = blockIdx.y * BM;
    const int col0 = blockIdx.x * BN;

    float c[4][4][4];
    #pragma unroll
    for (int i = 0; i < 4; ++i)
        #pragma unroll
        for (int j = 0; j < 4; ++j)
            #pragma unroll
            for (int q = 0; q < 4; ++q) c[i][j][q] = 0.f;

    const int nchunk = K / BK;

    auto load_stage = [&](int s, int kt) {
        uint32_t sa = sbase + (uint32_t)(s * STAGE_FLTS) * 4u;
        uint32_t sb = sa + 128u * SROW * 4u;
        const float* Ab = A  + (size_t)row0 * K + kt * BK;
        const float* Bb = Bt + (size_t)col0 * K + kt * BK;
        #pragma unroll
        for (int it = 0; it < 4; ++it) {
            int idx = it * 256 + tid;          // 0..1023
            int r   = idx >> 3;                // 0..127
            int c4  = (idx & 7) * 4;           // 0..28
            uint32_t off = (uint32_t)(r * SROW + c4) * 4u;
            CP_ASYNC16(sa + off, Ab + (size_t)r * K + c4);
            CP_ASYNC16(sb + off, Bb + (size_t)r * K + c4);
        }
    };

    load_stage(0, 0); CP_COMMIT();
    load_stage(1, 1); CP_COMMIT();

    for (int kt = 0; kt < nchunk; ++kt) {
        CP_WAIT(1);
        __syncthreads();
        if (kt + 2 < nchunk) load_stage((kt + 2) % NST, kt + 2);
        CP_COMMIT();

        const float* sa = sm + (kt % NST) * STAGE_FLTS;
        const float* sb = sa + 128 * SROW;
        #pragma unroll
        for (int ks = 0; ks < 4; ++ks) {
            const int kb = ks * 8;
            uint32_t af[4][4], bf[4][2];
            #pragma unroll
            for (int mt = 0; mt < 4; ++mt) {
                int r0 = wr * 64 + mt * 16 + (lane >> 2);
                int cA = kb + (lane & 3);
                af[mt][0] = f2tf(sa[r0 * SROW + cA]);
                af[mt][1] = f2tf(sa[(r0 + 8) * SROW + cA]);
                af[mt][2] = f2tf(sa[r0 * SROW + cA + 4]);
                af[mt][3] = f2tf(sa[(r0 + 8) * SROW + cA + 4]);
            }
            #pragma unroll
            for (int nt = 0; nt < 4; ++nt) {
                int n0 = wc * 32 + nt * 8 + (lane >> 2);
                bf[nt][0] = f2tf(sb[n0 * SROW + kb + (lane & 3)]);
                bf[nt][1] = f2tf(sb[n0 * SROW + kb + (lane & 3) + 4]);
            }
            #pragma unroll
            for (int mt = 0; mt < 4; ++mt)
                #pragma unroll
                for (int nt = 0; nt < 4; ++nt)
                    mma_tf32(c[mt][nt], af[mt], bf[nt]);
        }
    }

    // Epilogue: fragment layout c0,c1 -> (row, col..col+1); c2,c3 -> row+8
    #pragma unroll
    for (int mt = 0; mt < 4; ++mt) {
        #pragma unroll
        for (int nt = 0; nt < 4; ++nt) {
            int r   = row0 + wr * 64 + mt * 16 + (lane >> 2);
            int col = col0 + wc * 32 + nt * 8 + (lane & 3) * 2;
            float2 bv = *(const float2*)&bias[col];
            float2 o0 = make_float2(c[mt][nt][0] + bv.x, c[mt][nt][1] + bv.y);
            float2 o1 = make_float2(c[mt][nt][2] + bv.x, c[mt][nt][3] + bv.y);
            *(float2*)&C[(size_t)r * N + col]       = o0;
            *(float2*)&C[(size_t)(r + 8) * N + col] = o1;
        }
    }
}

// ---------------------------------------------------------------------------
// Weight transpose: out[c*R + r] = in[r*Ccols + c]
// ---------------------------------------------------------------------------
__global__ __launch_bounds__(256) void transpose_k(
    const float* __restrict__ in, float* __restrict__ out, int R, int Ccols)
{
    __shared__ float t[32][33];
    int r0 = blockIdx.y * 32, c0 = blockIdx.x * 32;
    #pragma unroll
    for (int i = threadIdx.y; i < 32; i += 8)
        t[i][threadIdx.x] = in[(size_t)(r0 + i) * Ccols + c0 + threadIdx.x];
    __syncthreads();
    #pragma unroll
    for (int i = threadIdx.y; i < 32; i += 8)
        out[(size_t)(c0 + i) * R + r0 + threadIdx.x] = t[threadIdx.x][i];
}

// ---------------------------------------------------------------------------
// Flash attention (causal), fp32 SIMT (unchanged from R1 — known good)
// ---------------------------------------------------------------------------
__global__ __launch_bounds__(128) void flash_attn(
    const float* __restrict__ qkv, float* __restrict__ y)
{
    __shared__ float Qs[64][68];
    __shared__ float Ks[32][68];
    __shared__ float Vs[32][68];
    __shared__ float Ps[64][36];

    const int tid = threadIdx.x;
    const int q0  = blockIdx.x * 64;
    const int h   = blockIdx.y;
    const int b   = blockIdx.z;
    const int r   = tid >> 1;
    const int hh  = tid & 1;

    const size_t base = (size_t)b * TSEQ * QKV_N + h * HDIM;

    for (int i = tid; i < 64 * 16; i += 128) {
        int row = i >> 4;
        int c4  = (i & 15) * 4;
        *(float4*)&Qs[row][c4] =
            *(const float4*)&qkv[base + (size_t)(q0 + row) * QKV_N + c4];
    }

    float m = -INFINITY, l = 0.f;
    float acc[32];
    #pragma unroll
    for (int i = 0; i < 32; ++i) acc[i] = 0.f;

    const int q = q0 + r;
    const int ntiles = (q0 + 64) / 32;
    const float scale = 0.125f;

    for (int t = 0; t < ntiles; ++t) {
        const int j0 = t * 32;
        __syncthreads();
        for (int i = tid; i < 32 * 16; i += 128) {
            int row = i >> 4;
            int c4  = (i & 15) * 4;
            size_t rowoff = base + (size_t)(j0 + row) * QKV_N + c4;
            *(float4*)&Ks[row][c4] = *(const float4*)&qkv[rowoff + CDIM];
            *(float4*)&Vs[row][c4] = *(const float4*)&qkv[rowoff + 2 * CDIM];
        }
        __syncthreads();

        float s[16];
        #pragma unroll
        for (int jj = 0; jj < 16; ++jj) s[jj] = 0.f;
        #pragma unroll
        for (int kk4 = 0; kk4 < 16; ++kk4) {
            float4 qv = *(const float4*)&Qs[r][kk4 * 4];
            #pragma unroll
            for (int jj = 0; jj < 16; ++jj) {
                float4 kv = *(const float4*)&Ks[hh * 16 + jj][kk4 * 4];
                s[jj] += qv.x * kv.x + qv.y * kv.y + qv.z * kv.z + qv.w * kv.w;
            }
        }

        if (j0 + 31 > q) {
            #pragma unroll
            for (int jj = 0; jj < 16; ++jj)
                s[jj] = (j0 + hh * 16 + jj <= q) ? s[jj] * scale : -INFINITY;
        } else {
            #pragma unroll
            for (int jj = 0; jj < 16; ++jj) s[jj] *= scale;
        }

        float mloc = s[0];
        #pragma unroll
        for (int jj = 1; jj < 16; ++jj) mloc = fmaxf(mloc, s[jj]);
        mloc = fmaxf(mloc, __shfl_xor_sync(0xffffffffu, mloc, 1));
        float mnew = fmaxf(m, mloc);
        float psum = 0.f;
        #pragma unroll
        for (int jj = 0; jj < 16; ++jj) {
            s[jj] = __expf(s[jj] - mnew);
            psum += s[jj];
        }
        psum += __shfl_xor_sync(0xffffffffu, psum, 1);
        float corr = __expf(m - mnew);
        l = l * corr + psum;
        m = mnew;
        #pragma unroll
        for (int i = 0; i < 32; ++i) acc[i] *= corr;

        #pragma unroll
        for (int jj = 0; jj < 16; ++jj) Ps[r][hh * 16 + jj] = s[jj];
        __syncwarp();

        #pragma unroll
        for (int j = 0; j < 32; ++j) {
            float p = Ps[r][j];
            const float4* vrow = (const float4*)&Vs[j][hh * 32];
            #pragma unroll
            for (int d4 = 0; d4 < 8; ++d4) {
                float4 v = vrow[d4];
                acc[d4 * 4 + 0] += p * v.x;
                acc[d4 * 4 + 1] += p * v.y;
                acc[d4 * 4 + 2] += p * v.z;
                acc[d4 * 4 + 3] += p * v.w;
            }
        }
    }

    const float inv = 1.f / l;
    float* yout = &y[((size_t)b * TSEQ + q) * CDIM + h * HDIM + hh * 32];
    #pragma unroll
    for (int d4 = 0; d4 < 8; ++d4) {
        float4 o;
        o.x = acc[d4 * 4 + 0] * inv;
        o.y = acc[d4 * 4 + 1] * inv;
        o.z = acc[d4 * 4 + 2] * inv;
        o.w = acc[d4 * 4 + 3] * inv;
        *(float4*)&yout[d4 * 4] = o;
    }
}

// ---------------------------------------------------------------------------
extern "C" void kernel_launch(void* const* d_in, const int* in_sizes, int n_in,
                              void* d_out, int out_size)
{
    const float* x     = (const float*)d_in[0];
    const float* W_qkv = (const float*)d_in[1];
    const float* b_qkv = (const float*)d_in[2];
    const float* W_o   = (const float*)d_in[3];
    const float* b_o   = (const float*)d_in[4];
    float* out = (float*)d_out;

    float *qkv_ptr, *y_ptr, *wtq_ptr, *wto_ptr;
    cudaGetSymbolAddress((void**)&qkv_ptr, g_qkv);
    cudaGetSymbolAddress((void**)&y_ptr,   g_y);
    cudaGetSymbolAddress((void**)&wtq_ptr, g_wt_qkv);
    cudaGetSymbolAddress((void**)&wto_ptr, g_wt_o);

    cudaFuncSetAttribute(gemm_mma, cudaFuncAttributeMaxDynamicSharedMemorySize, GEMM_SMEM);

    // Transpose weights to K-major ([N,K])
    transpose_k<<<dim3(QKV_N / 32, CDIM / 32), dim3(32, 8)>>>(W_qkv, wtq_ptr, CDIM, QKV_N);
    transpose_k<<<dim3(CDIM / 32, CDIM / 32), dim3(32, 8)>>>(W_o, wto_ptr, CDIM, CDIM);

    // qkv = x @ W_qkv + b_qkv   [4096, 3072]
    gemm_mma<<<dim3(QKV_N / BN, MROWS / BM), 256, GEMM_SMEM>>>(
        x, wtq_ptr, b_qkv, qkv_ptr, MROWS, QKV_N, CDIM);

    // y = attention(qkv)
    flash_attn<<<dim3(TSEQ / 64, NHEAD, BATCH), 128>>>(qkv_ptr, y_ptr);

    // out = y @ W_o + b_o       [4096, 1024]
    gemm_mma<<<dim3(CDIM / BN, MROWS / BM), 256, GEMM_SMEM>>>(
        y_ptr, wto_ptr, b_o, out, MROWS, CDIM, CDIM);
}

// round 4
// speedup vs baseline: 2.8443x; 2.1773x over previous
#include <cuda_runtime.h>
#include <math.h>
#include <cstdint>

#define BATCH 2
#define TSEQ  2048
#define CDIM  1024
#define NHEAD 16
#define HDIM  64
#define MROWS (BATCH*TSEQ)          // 4096
#define QKV_N (3*CDIM)              // 3072

// Scratch (no runtime allocation allowed)
__device__ float g_qkv[MROWS * QKV_N];     // [B*T, 3C]
__device__ float g_y  [MROWS * CDIM];      // [B*T, C]
__device__ float g_wt_qkv[QKV_N * CDIM];   // W_qkv^T  [3C, C]
__device__ float g_wt_o  [CDIM * CDIM];    // W_o^T    [C, C]

// ---------------------------------------------------------------------------
// helpers
// ---------------------------------------------------------------------------
__device__ __forceinline__ uint32_t smem_u32(const void* p) {
    uint32_t a;
    asm("{ .reg .u64 t; cvta.to.shared.u64 t, %1; cvt.u32.u64 %0, t; }" : "=r"(a) : "l"(p));
    return a;
}
__device__ __forceinline__ uint32_t f2tf(float f) {
    uint32_t u;
    asm("cvt.rna.tf32.f32 %0, %1;" : "=r"(u) : "f"(f));
    return u;
}
#define CP_ASYNC16(dst, src) \
    asm volatile("cp.async.cg.shared.global [%0], [%1], 16;" :: "r"(dst), "l"(src) : "memory")
#define CP_COMMIT() asm volatile("cp.async.commit_group;" ::: "memory")
#define CP_WAIT(n)  asm volatile("cp.async.wait_group %0;" :: "n"(n) : "memory")

__device__ __forceinline__ void mma_tf32(float* c, const uint32_t* a, const uint32_t* b) {
    asm volatile(
        "mma.sync.aligned.m16n8k8.row.col.f32.tf32.tf32.f32 "
        "{%0,%1,%2,%3}, {%4,%5,%6,%7}, {%8,%9}, {%0,%1,%2,%3};"
        : "+f"(c[0]), "+f"(c[1]), "+f"(c[2]), "+f"(c[3])
        : "r"(a[0]), "r"(a[1]), "r"(a[2]), "r"(a[3]), "r"(b[0]), "r"(b[1]));
}

// ---------------------------------------------------------------------------
// mma.sync tf32 GEMM: C[M,N] = A[M,K] @ Bt[N,K]^T + bias[N]
// CTA 128x128, BK=32, 3-stage cp.async, 8 warps, warp tile 64x32.
// ROUND: round outputs to tf32 (for qkv feeding the attention kernel).
// ---------------------------------------------------------------------------
#define BM 128
#define BN 128
#define BK 32
#define NST 3
#define SROW 36
#define STAGE_FLTS (2 * 128 * SROW)
#define GEMM_SMEM  (NST * STAGE_FLTS * 4)           // 110592 bytes

template <bool ROUND>
__global__ __launch_bounds__(256, 1) void gemm_mma(
    const float* __restrict__ A, const float* __restrict__ Bt,
    const float* __restrict__ bias, float* __restrict__ C,
    int M, int N, int K)
{
    extern __shared__ float sm[];
    const uint32_t sbase = smem_u32(sm);
    const int tid  = threadIdx.x;
    const int lane = tid & 31;
    const int w    = tid >> 5;
    const int wr   = w >> 2;
    const int wc   = w & 3;
    const int row0 = blockIdx.y * BM;
    const int col0 = blockIdx.x * BN;

    float c[4][4][4];
    #pragma unroll
    for (int i = 0; i < 4; ++i)
        #pragma unroll
        for (int j = 0; j < 4; ++j)
            #pragma unroll
            for (int q = 0; q < 4; ++q) c[i][j][q] = 0.f;

    const int nchunk = K / BK;

    auto load_stage = [&](int s, int kt) {
        uint32_t sa = sbase + (uint32_t)(s * STAGE_FLTS) * 4u;
        uint32_t sb = sa + 128u * SROW * 4u;
        const float* Ab = A  + (size_t)row0 * K + kt * BK;
        const float* Bb = Bt + (size_t)col0 * K + kt * BK;
        #pragma unroll
        for (int it = 0; it < 4; ++it) {
            int idx = it * 256 + tid;
            int r   = idx >> 3;
            int c4  = (idx & 7) * 4;
            uint32_t off = (uint32_t)(r * SROW + c4) * 4u;
            CP_ASYNC16(sa + off, Ab + (size_t)r * K + c4);
            CP_ASYNC16(sb + off, Bb + (size_t)r * K + c4);
        }
    };

    load_stage(0, 0); CP_COMMIT();
    load_stage(1, 1); CP_COMMIT();

    for (int kt = 0; kt < nchunk; ++kt) {
        CP_WAIT(1);
        __syncthreads();
        if (kt + 2 < nchunk) load_stage((kt + 2) % NST, kt + 2);
        CP_COMMIT();

        const float* sa = sm + (kt % NST) * STAGE_FLTS;
        const float* sb = sa + 128 * SROW;
        #pragma unroll
        for (int ks = 0; ks < 4; ++ks) {
            const int kb = ks * 8;
            uint32_t af[4][4], bf[4][2];
            #pragma unroll
            for (int mt = 0; mt < 4; ++mt) {
                int r0 = wr * 64 + mt * 16 + (lane >> 2);
                int cA = kb + (lane & 3);
                af[mt][0] = f2tf(sa[r0 * SROW + cA]);
                af[mt][1] = f2tf(sa[(r0 + 8) * SROW + cA]);
                af[mt][2] = f2tf(sa[r0 * SROW + cA + 4]);
                af[mt][3] = f2tf(sa[(r0 + 8) * SROW + cA + 4]);
            }
            #pragma unroll
            for (int nt = 0; nt < 4; ++nt) {
                int n0 = wc * 32 + nt * 8 + (lane >> 2);
                bf[nt][0] = f2tf(sb[n0 * SROW + kb + (lane & 3)]);
                bf[nt][1] = f2tf(sb[n0 * SROW + kb + (lane & 3) + 4]);
            }
            #pragma unroll
            for (int mt = 0; mt < 4; ++mt)
                #pragma unroll
                for (int nt = 0; nt < 4; ++nt)
                    mma_tf32(c[mt][nt], af[mt], bf[nt]);
        }
    }

    #pragma unroll
    for (int mt = 0; mt < 4; ++mt) {
        #pragma unroll
        for (int nt = 0; nt < 4; ++nt) {
            int r   = row0 + wr * 64 + mt * 16 + (lane >> 2);
            int col = col0 + wc * 32 + nt * 8 + (lane & 3) * 2;
            float2 bv = *(const float2*)&bias[col];
            float v00 = c[mt][nt][0] + bv.x, v01 = c[mt][nt][1] + bv.y;
            float v10 = c[mt][nt][2] + bv.x, v11 = c[mt][nt][3] + bv.y;
            if (ROUND) {
                v00 = __uint_as_float(f2tf(v00));
                v01 = __uint_as_float(f2tf(v01));
                v10 = __uint_as_float(f2tf(v10));
                v11 = __uint_as_float(f2tf(v11));
            }
            *(float2*)&C[(size_t)r * N + col]       = make_float2(v00, v01);
            *(float2*)&C[(size_t)(r + 8) * N + col] = make_float2(v10, v11);
        }
    }
}

// ---------------------------------------------------------------------------
// Weight transpose: out[c*R + r] = in[r*Ccols + c]
// ---------------------------------------------------------------------------
__global__ __launch_bounds__(256) void transpose_k(
    const float* __restrict__ in, float* __restrict__ out, int R, int Ccols)
{
    __shared__ float t[32][33];
    int r0 = blockIdx.y * 32, c0 = blockIdx.x * 32;
    #pragma unroll
    for (int i = threadIdx.y; i < 32; i += 8)
        t[i][threadIdx.x] = in[(size_t)(r0 + i) * Ccols + c0 + threadIdx.x];
    __syncthreads();
    #pragma unroll
    for (int i = threadIdx.y; i < 32; i += 8)
        out[(size_t)(c0 + i) * R + r0 + threadIdx.x] = t[threadIdx.x][i];
}

// ---------------------------------------------------------------------------
// Flash attention (causal) with mma.sync tf32.
// Block: 128 queries x one (b,h). 8 warps; warp w owns rows w*16..w*16+15.
// KV tiles of 64 keys, double-buffered cp.async.
// qkv values are already tf32-rounded (GEMM epilogue) -> no per-use cvt.
// ---------------------------------------------------------------------------
#define AQ 128
#define AKV 64
#define QSTR 68
#define KSTR 68
#define VSTR 72
#define SM_QS 0
#define SM_KS (AQ * QSTR)                       // 8704
#define SM_VS (SM_KS + 2 * AKV * KSTR)          // +8704
#define ATTN_SMEM ((SM_VS + 2 * AKV * VSTR) * 4)  // 106496 bytes

__global__ __launch_bounds__(256, 1) void attn_mma(
    const float* __restrict__ qkv, float* __restrict__ y)
{
    extern __shared__ float sm[];
    const uint32_t sb = smem_u32(sm);
    const int tid  = threadIdx.x;
    const int lane = tid & 31;
    const int w    = tid >> 5;
    const int g    = lane >> 2;   // row-in-group
    const int la3  = lane & 3;

    const int qblk = (gridDim.x - 1) - blockIdx.x;   // heavy blocks first
    const int q0   = qblk * AQ;
    const int h    = blockIdx.y;
    const int b    = blockIdx.z;
    const size_t base = (size_t)b * TSEQ * QKV_N + h * HDIM;

    // Load Q tile (scaled by 1/8, exact on tf32 values)
    for (int i = tid; i < AQ * 16; i += 256) {
        int r = i >> 4, c = (i & 15) * 4;
        float4 v = *(const float4*)&qkv[base + (size_t)(q0 + r) * QKV_N + c];
        v.x *= 0.125f; v.y *= 0.125f; v.z *= 0.125f; v.w *= 0.125f;
        *(float4*)&sm[SM_QS + r * QSTR + c] = v;
    }

    const int ntile = q0 / AKV + 2;

    auto load_kv = [&](int t, int stage) {
        uint32_t ks_ = sb + (uint32_t)(SM_KS + stage * AKV * KSTR) * 4u;
        uint32_t vs_ = sb + (uint32_t)(SM_VS + stage * AKV * VSTR) * 4u;
        const float* Kg = qkv + base + CDIM     + (size_t)t * AKV * QKV_N;
        const float* Vg = qkv + base + 2 * CDIM + (size_t)t * AKV * QKV_N;
        #pragma unroll
        for (int it = 0; it < 4; ++it) {
            int idx = it * 256 + tid;       // 0..1023
            int r = idx >> 4;               // key 0..63
            int c = (idx & 15) * 4;         // dim chunk
            CP_ASYNC16(ks_ + (uint32_t)(r * KSTR + c) * 4u, Kg + (size_t)r * QKV_N + c);
            CP_ASYNC16(vs_ + (uint32_t)(r * VSTR + c) * 4u, Vg + (size_t)r * QKV_N + c);
        }
    };

    load_kv(0, 0); CP_COMMIT();
    __syncthreads();    // Qs visible

    // Q fragments in registers (reused across all KV tiles)
    uint32_t qf[8][4];
    const int rl1 = w * 16 + g;             // local row
    #pragma unroll
    for (int ks = 0; ks < 8; ++ks) {
        qf[ks][0] = __float_as_uint(sm[SM_QS + rl1 * QSTR + ks * 8 + la3]);
        qf[ks][1] = __float_as_uint(sm[SM_QS + (rl1 + 8) * QSTR + ks * 8 + la3]);
        qf[ks][2] = __float_as_uint(sm[SM_QS + rl1 * QSTR + ks * 8 + la3 + 4]);
        qf[ks][3] = __float_as_uint(sm[SM_QS + (rl1 + 8) * QSTR + ks * 8 + la3 + 4]);
    }

    float o[8][4];
    #pragma unroll
    for (int nt = 0; nt < 8; ++nt)
        #pragma unroll
        for (int q = 0; q < 4; ++q) o[nt][q] = 0.f;
    float m0 = -1e30f, m1 = -1e30f, l0 = 0.f, l1 = 0.f;

    const int row1 = q0 + rl1;      // global query row
    const int row2 = row1 + 8;

    for (int t = 0; t < ntile; ++t) {
        if (t + 1 < ntile) load_kv(t + 1, (t + 1) & 1);
        CP_COMMIT();
        CP_WAIT(1);
        __syncthreads();

        const float* Ks_ = &sm[SM_KS + (t & 1) * AKV * KSTR];
        const float* Vs_ = &sm[SM_VS + (t & 1) * AKV * VSTR];

        // S = Q K^T
        float s[8][4];
        #pragma unroll
        for (int nt = 0; nt < 8; ++nt)
            #pragma unroll
            for (int q = 0; q < 4; ++q) s[nt][q] = 0.f;
        #pragma unroll
        for (int ks = 0; ks < 8; ++ks) {
            #pragma unroll
            for (int nt = 0; nt < 8; ++nt) {
                uint32_t bf[2];
                bf[0] = __float_as_uint(Ks_[(nt * 8 + g) * KSTR + ks * 8 + la3]);
                bf[1] = __float_as_uint(Ks_[(nt * 8 + g) * KSTR + ks * 8 + la3 + 4]);
                mma_tf32(s[nt], qf[ks], bf);
            }
        }

        const int j0 = t * AKV;
        if (j0 >= q0) {   // diagonal region: causal mask
            #pragma unroll
            for (int nt = 0; nt < 8; ++nt) {
                int col = j0 + nt * 8 + 2 * la3;
                if (col     > row1) s[nt][0] = -1e30f;
                if (col + 1 > row1) s[nt][1] = -1e30f;
                if (col     > row2) s[nt][2] = -1e30f;
                if (col + 1 > row2) s[nt][3] = -1e30f;
            }
        }

        // row max over tile
        float mx0 = -1e30f, mx1 = -1e30f;
        #pragma unroll
        for (int nt = 0; nt < 8; ++nt) {
            mx0 = fmaxf(mx0, fmaxf(s[nt][0], s[nt][1]));
            mx1 = fmaxf(mx1, fmaxf(s[nt][2], s[nt][3]));
        }
        mx0 = fmaxf(mx0, __shfl_xor_sync(0xffffffffu, mx0, 1));
        mx0 = fmaxf(mx0, __shfl_xor_sync(0xffffffffu, mx0, 2));
        mx1 = fmaxf(mx1, __shfl_xor_sync(0xffffffffu, mx1, 1));
        mx1 = fmaxf(mx1, __shfl_xor_sync(0xffffffffu, mx1, 2));

        float M0 = fmaxf(m0, mx0), M1 = fmaxf(m1, mx1);
        float corr0 = __expf(m0 - M0), corr1 = __expf(m1 - M1);
        m0 = M0; m1 = M1;

        #pragma unroll
        for (int nt = 0; nt < 8; ++nt) {
            o[nt][0] *= corr0; o[nt][1] *= corr0;
            o[nt][2] *= corr1; o[nt][3] *= corr1;
        }

        float ps0 = 0.f, ps1 = 0.f;

        // Per k-step: exp, tf32-round, shfl-repack to A-fragment, PV mma
        #pragma unroll
        for (int ks = 0; ks < 8; ++ks) {
            uint32_t p0 = f2tf(__expf(s[ks][0] - M0));
            uint32_t p1 = f2tf(__expf(s[ks][1] - M0));
            uint32_t p2 = f2tf(__expf(s[ks][2] - M1));
            uint32_t p3 = f2tf(__expf(s[ks][3] - M1));
            ps0 += __uint_as_float(p0) + __uint_as_float(p1);
            ps1 += __uint_as_float(p2) + __uint_as_float(p3);

            int srcA = (lane & ~3) | (la3 >> 1);
            int srcB = srcA + 2;
            uint32_t v0 = __shfl_sync(0xffffffffu, p0, srcA);
            uint32_t v1 = __shfl_sync(0xffffffffu, p1, srcA);
            uint32_t v2 = __shfl_sync(0xffffffffu, p2, srcA);
            uint32_t v3 = __shfl_sync(0xffffffffu, p3, srcA);
            uint32_t u0 = __shfl_sync(0xffffffffu, p0, srcB);
            uint32_t u1 = __shfl_sync(0xffffffffu, p1, srcB);
            uint32_t u2 = __shfl_sync(0xffffffffu, p2, srcB);
            uint32_t u3 = __shfl_sync(0xffffffffu, p3, srcB);
            bool odd = (la3 & 1);
            uint32_t af[4];
            af[0] = odd ? v1 : v0;
            af[1] = odd ? v3 : v2;
            af[2] = odd ? u1 : u0;
            af[3] = odd ? u3 : u2;

            #pragma unroll
            for (int nt = 0; nt < 8; ++nt) {
                uint32_t bf[2];
                bf[0] = __float_as_uint(Vs_[(ks * 8 + la3) * VSTR + nt * 8 + g]);
                bf[1] = __float_as_uint(Vs_[(ks * 8 + la3 + 4) * VSTR + nt * 8 + g]);
                mma_tf32(o[nt], af, bf);
            }
        }

        ps0 += __shfl_xor_sync(0xffffffffu, ps0, 1);
        ps0 += __shfl_xor_sync(0xffffffffu, ps0, 2);
        ps1 += __shfl_xor_sync(0xffffffffu, ps1, 1);
        ps1 += __shfl_xor_sync(0xffffffffu, ps1, 2);
        l0 = l0 * corr0 + ps0;
        l1 = l1 * corr1 + ps1;

        __syncthreads();   // all warps done with this stage before reuse
    }

    const float inv0 = 1.f / l0, inv1 = 1.f / l1;
    float* y1 = &y[((size_t)b * TSEQ + row1) * CDIM + h * HDIM];
    float* y2 = &y[((size_t)b * TSEQ + row2) * CDIM + h * HDIM];
    #pragma unroll
    for (int nt = 0; nt < 8; ++nt) {
        int col = nt * 8 + 2 * la3;
        *(float2*)&y1[col] = make_float2(o[nt][0] * inv0, o[nt][1] * inv0);
        *(float2*)&y2[col] = make_float2(o[nt][2] * inv1, o[nt][3] * inv1);
    }
}

// ---------------------------------------------------------------------------
extern "C" void kernel_launch(void* const* d_in, const int* in_sizes, int n_in,
                              void* d_out, int out_size)
{
    const float* x     = (const float*)d_in[0];
    const float* W_qkv = (const float*)d_in[1];
    const float* b_qkv = (const float*)d_in[2];
    const float* W_o   = (const float*)d_in[3];
    const float* b_o   = (const float*)d_in[4];
    float* out = (float*)d_out;

    float *qkv_ptr, *y_ptr, *wtq_ptr, *wto_ptr;
    cudaGetSymbolAddress((void**)&qkv_ptr, g_qkv);
    cudaGetSymbolAddress((void**)&y_ptr,   g_y);
    cudaGetSymbolAddress((void**)&wtq_ptr, g_wt_qkv);
    cudaGetSymbolAddress((void**)&wto_ptr, g_wt_o);

    cudaFuncSetAttribute(gemm_mma<true>,  cudaFuncAttributeMaxDynamicSharedMemorySize, GEMM_SMEM);
    cudaFuncSetAttribute(gemm_mma<false>, cudaFuncAttributeMaxDynamicSharedMemorySize, GEMM_SMEM);
    cudaFuncSetAttribute(attn_mma, cudaFuncAttributeMaxDynamicSharedMemorySize, ATTN_SMEM);

    // Transpose weights to K-major ([N,K])
    transpose_k<<<dim3(QKV_N / 32, CDIM / 32), dim3(32, 8)>>>(W_qkv, wtq_ptr, CDIM, QKV_N);
    transpose_k<<<dim3(CDIM / 32, CDIM / 32), dim3(32, 8)>>>(W_o, wto_ptr, CDIM, CDIM);

    // qkv = tf32_round(x @ W_qkv + b_qkv)   [4096, 3072]
    gemm_mma<true><<<dim3(QKV_N / BN, MROWS / BM), 256, GEMM_SMEM>>>(
        x, wtq_ptr, b_qkv, qkv_ptr, MROWS, QKV_N, CDIM);

    // y = attention(qkv)
    attn_mma<<<dim3(TSEQ / AQ, NHEAD, BATCH), 256, ATTN_SMEM>>>(qkv_ptr, y_ptr);

    // out = y @ W_o + b_o       [4096, 1024]
    gemm_mma<false><<<dim3(CDIM / BN, MROWS / BM), 256, GEMM_SMEM>>>(
        y_ptr, wto_ptr, b_o, out, MROWS, CDIM, CDIM);
}

// round 5
// speedup vs baseline: 4.9338x; 1.7347x over previous
#include <cuda_runtime.h>
#include <math.h>
#include <cstdint>

#define BATCH 2
#define TSEQ  2048
#define CDIM  1024
#define NHEAD 16
#define HDIM  64
#define MROWS (BATCH*TSEQ)          // 4096
#define QKV_N (3*CDIM)              // 3072

// Scratch (no runtime allocation allowed)
__device__ float g_qkv[MROWS * QKV_N];     // [B*T, 3C]  (tf32-rounded)
__device__ float g_y  [MROWS * CDIM];      // [B*T, C]   (tf32-rounded)
__device__ float g_x  [MROWS * CDIM];      // tf32-rounded copy of x
__device__ float g_wt_qkv[QKV_N * CDIM];   // W_qkv^T  (tf32-rounded)
__device__ float g_wt_o  [CDIM * CDIM];    // W_o^T    (tf32-rounded)

// ---------------------------------------------------------------------------
// helpers
// ---------------------------------------------------------------------------
__device__ __forceinline__ uint32_t smem_u32(const void* p) {
    uint32_t a;
    asm("{ .reg .u64 t; cvta.to.shared.u64 t, %1; cvt.u32.u64 %0, t; }" : "=r"(a) : "l"(p));
    return a;
}
__device__ __forceinline__ uint32_t f2tf(float f) {
    uint32_t u;
    asm("cvt.rna.tf32.f32 %0, %1;" : "=r"(u) : "f"(f));
    return u;
}
__device__ __forceinline__ float f2tf_f(float f) { return __uint_as_float(f2tf(f)); }

#define CP_ASYNC16(dst, src) \
    asm volatile("cp.async.cg.shared.global [%0], [%1], 16;" :: "r"(dst), "l"(src) : "memory")
#define CP_COMMIT() asm volatile("cp.async.commit_group;" ::: "memory")
#define CP_WAIT(n)  asm volatile("cp.async.wait_group %0;" :: "n"(n) : "memory")

__device__ __forceinline__ void mma_tf32(float* c, const uint32_t* a, const uint32_t* b) {
    asm volatile(
        "mma.sync.aligned.m16n8k8.row.col.f32.tf32.tf32.f32 "
        "{%0,%1,%2,%3}, {%4,%5,%6,%7}, {%8,%9}, {%0,%1,%2,%3};"
        : "+f"(c[0]), "+f"(c[1]), "+f"(c[2]), "+f"(c[3])
        : "r"(a[0]), "r"(a[1]), "r"(a[2]), "r"(a[3]), "r"(b[0]), "r"(b[1]));
}

// ---------------------------------------------------------------------------
// mma.sync tf32 GEMM: C[M,N] = A[M,K] @ Bt[N,K]^T + bias[N]
// Inputs are pre-rounded to tf32 (no cvt in mainloop).
// k-permuted fragments: all fragment loads are float2 (64-bit LDS).
// CTA 128x128, BK=32, 3-stage cp.async, 8 warps, warp tile 64x32.
// ---------------------------------------------------------------------------
#define BM 128
#define BN 128
#define BK 32
#define NST 3
#define SROW 40                                  // == 8 mod 32: conflict-free LDS.64
#define STAGE_FLTS (2 * 128 * SROW)
#define GEMM_SMEM  (NST * STAGE_FLTS * 4)        // 122880 bytes

template <bool ROUND>
__global__ __launch_bounds__(256, 1) void gemm_mma(
    const float* __restrict__ A, const float* __restrict__ Bt,
    const float* __restrict__ bias, float* __restrict__ C,
    int M, int N, int K)
{
    extern __shared__ float sm[];
    const uint32_t sbase = smem_u32(sm);
    const int tid  = threadIdx.x;
    const int lane = tid & 31;
    const int w    = tid >> 5;
    const int wr   = w >> 2;
    const int wc   = w & 3;
    const int g    = lane >> 2;
    const int la3  = lane & 3;
    const int row0 = blockIdx.y * BM;
    const int col0 = blockIdx.x * BN;

    float c[4][4][4];
    #pragma unroll
    for (int i = 0; i < 4; ++i)
        #pragma unroll
        for (int j = 0; j < 4; ++j)
            #pragma unroll
            for (int q = 0; q < 4; ++q) c[i][j][q] = 0.f;

    const int nchunk = K / BK;

    auto load_stage = [&](int s, int kt) {
        uint32_t sa = sbase + (uint32_t)(s * STAGE_FLTS) * 4u;
        uint32_t sb = sa + 128u * SROW * 4u;
        const float* Ab = A  + (size_t)row0 * K + kt * BK;
        const float* Bb = Bt + (size_t)col0 * K + kt * BK;
        #pragma unroll
        for (int it = 0; it < 4; ++it) {
            int idx = it * 256 + tid;
            int r   = idx >> 3;
            int c4  = (idx & 7) * 4;
            uint32_t off = (uint32_t)(r * SROW + c4) * 4u;
            CP_ASYNC16(sa + off, Ab + (size_t)r * K + c4);
            CP_ASYNC16(sb + off, Bb + (size_t)r * K + c4);
        }
    };

    load_stage(0, 0); CP_COMMIT();
    load_stage(1, 1); CP_COMMIT();

    for (int kt = 0; kt < nchunk; ++kt) {
        CP_WAIT(1);
        __syncthreads();
        if (kt + 2 < nchunk) load_stage((kt + 2) % NST, kt + 2);
        CP_COMMIT();

        const float* sa = sm + (kt % NST) * STAGE_FLTS;
        const float* sb = sa + 128 * SROW;
        #pragma unroll
        for (int ks = 0; ks < 4; ++ks) {
            const int kb = ks * 8 + 2 * la3;     // k-permuted pair base
            uint32_t af[4][4], bf[4][2];
            #pragma unroll
            for (int mt = 0; mt < 4; ++mt) {
                int r0 = wr * 64 + mt * 16 + g;
                float2 a02 = *(const float2*)&sa[r0 * SROW + kb];
                float2 a13 = *(const float2*)&sa[(r0 + 8) * SROW + kb];
                af[mt][0] = __float_as_uint(a02.x);
                af[mt][2] = __float_as_uint(a02.y);
                af[mt][1] = __float_as_uint(a13.x);
                af[mt][3] = __float_as_uint(a13.y);
            }
            #pragma unroll
            for (int nt = 0; nt < 4; ++nt) {
                int n0 = wc * 32 + nt * 8 + g;
                float2 b01 = *(const float2*)&sb[n0 * SROW + kb];
                bf[nt][0] = __float_as_uint(b01.x);
                bf[nt][1] = __float_as_uint(b01.y);
            }
            #pragma unroll
            for (int mt = 0; mt < 4; ++mt)
                #pragma unroll
                for (int nt = 0; nt < 4; ++nt)
                    mma_tf32(c[mt][nt], af[mt], bf[nt]);
        }
    }

    #pragma unroll
    for (int mt = 0; mt < 4; ++mt) {
        #pragma unroll
        for (int nt = 0; nt < 4; ++nt) {
            int r   = row0 + wr * 64 + mt * 16 + g;
            int col = col0 + wc * 32 + nt * 8 + la3 * 2;
            float2 bv = *(const float2*)&bias[col];
            float v00 = c[mt][nt][0] + bv.x, v01 = c[mt][nt][1] + bv.y;
            float v10 = c[mt][nt][2] + bv.x, v11 = c[mt][nt][3] + bv.y;
            if (ROUND) {
                v00 = f2tf_f(v00); v01 = f2tf_f(v01);
                v10 = f2tf_f(v10); v11 = f2tf_f(v11);
            }
            *(float2*)&C[(size_t)r * N + col]       = make_float2(v00, v01);
            *(float2*)&C[(size_t)(r + 8) * N + col] = make_float2(v10, v11);
        }
    }
}

// ---------------------------------------------------------------------------
// Weight transpose + tf32 round: out[c*R + r] = tf32(in[r*Ccols + c])
// ---------------------------------------------------------------------------
__global__ __launch_bounds__(256) void transpose_k(
    const float* __restrict__ in, float* __restrict__ out, int R, int Ccols)
{
    __shared__ float t[32][33];
    int r0 = blockIdx.y * 32, c0 = blockIdx.x * 32;
    #pragma unroll
    for (int i = threadIdx.y; i < 32; i += 8)
        t[i][threadIdx.x] = in[(size_t)(r0 + i) * Ccols + c0 + threadIdx.x];
    __syncthreads();
    #pragma unroll
    for (int i = threadIdx.y; i < 32; i += 8)
        out[(size_t)(c0 + i) * R + r0 + threadIdx.x] = f2tf_f(t[threadIdx.x][i]);
}

// ---------------------------------------------------------------------------
// Round x to tf32 into g_x
// ---------------------------------------------------------------------------
__global__ __launch_bounds__(256) void round_x(
    const float* __restrict__ in, float* __restrict__ out)
{
    int i = (blockIdx.x * 256 + threadIdx.x) * 4;
    float4 v = *(const float4*)&in[i];
    v.x = f2tf_f(v.x); v.y = f2tf_f(v.y); v.z = f2tf_f(v.z); v.w = f2tf_f(v.w);
    *(float4*)&out[i] = v;
}

// ---------------------------------------------------------------------------
// Flash attention (causal), mma.sync tf32, k-permuted fragments.
// Block: 128 queries x one (b,h). 8 warps x 16 rows. KV tiles of 64,
// double-buffered cp.async. V transposed in smem -> PV B-frags are float2.
// P repack is FREE: S accumulator layout == PV A-fragment layout under the
// k-permutation pi(la3)=2*la3, pi(la3+4)=2*la3+1.
// ---------------------------------------------------------------------------
#define AQ 128
#define AKV 64
#define ASTR 72                                 // == 8 mod 32: conflict-free LDS.64
#define VSTG 68                                 // == 4 mod 32: conflict-free LDS.128
#define SM_QS 0
#define SM_KS (AQ * ASTR)                       // 9216
#define SM_VST (SM_KS + 2 * AKV * ASTR)         // 18432
#define SM_VT  (SM_VST + 2 * AKV * VSTG)        // 27136
#define ATTN_SMEM ((SM_VT + 2 * AKV * ASTR) * 4)   // 145408 bytes

__global__ __launch_bounds__(256, 1) void attn_mma(
    const float* __restrict__ qkv, float* __restrict__ y)
{
    extern __shared__ float sm[];
    const uint32_t sb = smem_u32(sm);
    const int tid  = threadIdx.x;
    const int lane = tid & 31;
    const int w    = tid >> 5;
    const int g    = lane >> 2;
    const int la3  = lane & 3;

    const int qblk = (gridDim.x - 1) - blockIdx.x;   // heavy blocks first
    const int q0   = qblk * AQ;
    const int h    = blockIdx.y;
    const int b    = blockIdx.z;
    const size_t base = (size_t)b * TSEQ * QKV_N + h * HDIM;

    // Load Q tile (scaled by 1/8, exact on tf32 values)
    for (int i = tid; i < AQ * 16; i += 256) {
        int r = i >> 4, c = (i & 15) * 4;
        float4 v = *(const float4*)&qkv[base + (size_t)(q0 + r) * QKV_N + c];
        v.x *= 0.125f; v.y *= 0.125f; v.z *= 0.125f; v.w *= 0.125f;
        *(float4*)&sm[SM_QS + r * ASTR + c] = v;
    }

    const int ntile = q0 / AKV + 2;

    auto load_kv = [&](int t, int stage) {
        uint32_t ks_ = sb + (uint32_t)(SM_KS + stage * AKV * ASTR) * 4u;
        uint32_t vs_ = sb + (uint32_t)(SM_VST + stage * AKV * VSTG) * 4u;
        const float* Kg = qkv + base + CDIM     + (size_t)t * AKV * QKV_N;
        const float* Vg = qkv + base + 2 * CDIM + (size_t)t * AKV * QKV_N;
        #pragma unroll
        for (int it = 0; it < 4; ++it) {
            int idx = it * 256 + tid;
            int r = idx >> 4;               // key 0..63
            int c = (idx & 15) * 4;
            CP_ASYNC16(ks_ + (uint32_t)(r * ASTR + c) * 4u, Kg + (size_t)r * QKV_N + c);
            CP_ASYNC16(vs_ + (uint32_t)(r * VSTG + c) * 4u, Vg + (size_t)r * QKV_N + c);
        }
    };

    load_kv(0, 0); CP_COMMIT();
    __syncthreads();    // Qs visible

    // Q fragments (k-permuted): float2 loads, reused across all KV tiles
    uint32_t qf[8][4];
    const int rl1 = w * 16 + g;
    #pragma unroll
    for (int ks = 0; ks < 8; ++ks) {
        float2 q02 = *(const float2*)&sm[SM_QS + rl1 * ASTR + ks * 8 + 2 * la3];
        float2 q13 = *(const float2*)&sm[SM_QS + (rl1 + 8) * ASTR + ks * 8 + 2 * la3];
        qf[ks][0] = __float_as_uint(q02.x);
        qf[ks][2] = __float_as_uint(q02.y);
        qf[ks][1] = __float_as_uint(q13.x);
        qf[ks][3] = __float_as_uint(q13.y);
    }

    float o[8][4];
    #pragma unroll
    for (int nt = 0; nt < 8; ++nt)
        #pragma unroll
        for (int q = 0; q < 4; ++q) o[nt][q] = 0.f;
    float m0 = -1e30f, m1 = -1e30f, l0 = 0.f, l1 = 0.f;

    const int row1 = q0 + rl1;
    const int row2 = row1 + 8;

    for (int t = 0; t < ntile; ++t) {
        if (t + 1 < ntile) load_kv(t + 1, (t + 1) & 1);
        CP_COMMIT();
        CP_WAIT(1);
        __syncthreads();

        const int par = t & 1;
        const float* Ks_  = &sm[SM_KS  + par * AKV * ASTR];
        const float* Vst_ = &sm[SM_VST + par * AKV * VSTG];
        float*       Vt_  = &sm[SM_VT  + par * AKV * ASTR];

        // Transpose V stage -> VT [dim][key] (STS; visible after next sync)
        #pragma unroll
        for (int it = 0; it < 4; ++it) {
            int idx = it * 256 + tid;
            int key = idx & 63;
            int c4  = (idx >> 6) * 4;
            float4 v = *(const float4*)&Vst_[key * VSTG + c4];
            Vt_[(c4 + 0) * ASTR + key] = v.x;
            Vt_[(c4 + 1) * ASTR + key] = v.y;
            Vt_[(c4 + 2) * ASTR + key] = v.z;
            Vt_[(c4 + 3) * ASTR + key] = v.w;
        }

        // S = Q K^T (k-permuted B frags: float2)
        float s[8][4];
        #pragma unroll
        for (int nt = 0; nt < 8; ++nt)
            #pragma unroll
            for (int q = 0; q < 4; ++q) s[nt][q] = 0.f;
        #pragma unroll
        for (int ks = 0; ks < 8; ++ks) {
            #pragma unroll
            for (int nt = 0; nt < 8; ++nt) {
                float2 kk = *(const float2*)&Ks_[(nt * 8 + g) * ASTR + ks * 8 + 2 * la3];
                uint32_t bf[2] = { __float_as_uint(kk.x), __float_as_uint(kk.y) };
                mma_tf32(s[nt], qf[ks], bf);
            }
        }

        const int j0 = t * AKV;
        if (j0 >= q0) {   // diagonal region: causal mask
            #pragma unroll
            for (int nt = 0; nt < 8; ++nt) {
                int col = j0 + nt * 8 + 2 * la3;
                if (col     > row1) s[nt][0] = -1e30f;
                if (col + 1 > row1) s[nt][1] = -1e30f;
                if (col     > row2) s[nt][2] = -1e30f;
                if (col + 1 > row2) s[nt][3] = -1e30f;
            }
        }

        // row max
        float mx0 = -1e30f, mx1 = -1e30f;
        #pragma unroll
        for (int nt = 0; nt < 8; ++nt) {
            mx0 = fmaxf(mx0, fmaxf(s[nt][0], s[nt][1]));
            mx1 = fmaxf(mx1, fmaxf(s[nt][2], s[nt][3]));
        }
        mx0 = fmaxf(mx0, __shfl_xor_sync(0xffffffffu, mx0, 1));
        mx0 = fmaxf(mx0, __shfl_xor_sync(0xffffffffu, mx0, 2));
        mx1 = fmaxf(mx1, __shfl_xor_sync(0xffffffffu, mx1, 1));
        mx1 = fmaxf(mx1, __shfl_xor_sync(0xffffffffu, mx1, 2));

        float M0 = fmaxf(m0, mx0), M1 = fmaxf(m1, mx1);
        float corr0 = __expf(m0 - M0), corr1 = __expf(m1 - M1);
        m0 = M0; m1 = M1;

        #pragma unroll
        for (int nt = 0; nt < 8; ++nt) {
            o[nt][0] *= corr0; o[nt][1] *= corr0;
            o[nt][2] *= corr1; o[nt][3] *= corr1;
        }

        // P = exp(S - M) (tf32) stays in registers; layout matches PV A-frag
        float ps0 = 0.f, ps1 = 0.f;
        uint32_t pf[8][4];
        #pragma unroll
        for (int ks = 0; ks < 8; ++ks) {
            float p0 = f2tf_f(__expf(s[ks][0] - M0));
            float p1 = f2tf_f(__expf(s[ks][1] - M0));
            float p2 = f2tf_f(__expf(s[ks][2] - M1));
            float p3 = f2tf_f(__expf(s[ks][3] - M1));
            ps0 += p0 + p1;
            ps1 += p2 + p3;
            pf[ks][0] = __float_as_uint(p0);    // (row g,   k=2*la3)
            pf[ks][2] = __float_as_uint(p1);    // (row g,   k=2*la3+1)
            pf[ks][1] = __float_as_uint(p2);    // (row g+8, k=2*la3)
            pf[ks][3] = __float_as_uint(p3);    // (row g+8, k=2*la3+1)
        }

        ps0 += __shfl_xor_sync(0xffffffffu, ps0, 1);
        ps0 += __shfl_xor_sync(0xffffffffu, ps0, 2);
        ps1 += __shfl_xor_sync(0xffffffffu, ps1, 1);
        ps1 += __shfl_xor_sync(0xffffffffu, ps1, 2);
        l0 = l0 * corr0 + ps0;
        l1 = l1 * corr1 + ps1;

        __syncthreads();   // VT complete; all warps past K reads

        // O += P V (B frags from VT: float2)
        #pragma unroll
        for (int ks = 0; ks < 8; ++ks) {
            #pragma unroll
            for (int nt = 0; nt < 8; ++nt) {
                float2 vv = *(const float2*)&Vt_[(nt * 8 + g) * ASTR + ks * 8 + 2 * la3];
                uint32_t bf[2] = { __float_as_uint(vv.x), __float_as_uint(vv.y) };
                mma_tf32(o[nt], pf[ks], bf);
            }
        }
    }

    const float inv0 = 1.f / l0, inv1 = 1.f / l1;
    float* y1 = &y[((size_t)b * TSEQ + row1) * CDIM + h * HDIM];
    float* y2 = &y[((size_t)b * TSEQ + row2) * CDIM + h * HDIM];
    #pragma unroll
    for (int nt = 0; nt < 8; ++nt) {
        int col = nt * 8 + 2 * la3;
        *(float2*)&y1[col] = make_float2(f2tf_f(o[nt][0] * inv0), f2tf_f(o[nt][1] * inv0));
        *(float2*)&y2[col] = make_float2(f2tf_f(o[nt][2] * inv1), f2tf_f(o[nt][3] * inv1));
    }
}

// ---------------------------------------------------------------------------
extern "C" void kernel_launch(void* const* d_in, const int* in_sizes, int n_in,
                              void* d_out, int out_size)
{
    const float* x     = (const float*)d_in[0];
    const float* W_qkv = (const float*)d_in[1];
    const float* b_qkv = (const float*)d_in[2];
    const float* W_o   = (const float*)d_in[3];
    const float* b_o   = (const float*)d_in[4];
    float* out = (float*)d_out;

    float *qkv_ptr, *y_ptr, *x_ptr, *wtq_ptr, *wto_ptr;
    cudaGetSymbolAddress((void**)&qkv_ptr, g_qkv);
    cudaGetSymbolAddress((void**)&y_ptr,   g_y);
    cudaGetSymbolAddress((void**)&x_ptr,   g_x);
    cudaGetSymbolAddress((void**)&wtq_ptr, g_wt_qkv);
    cudaGetSymbolAddress((void**)&wto_ptr, g_wt_o);

    cudaFuncSetAttribute(gemm_mma<true>,  cudaFuncAttributeMaxDynamicSharedMemorySize, GEMM_SMEM);
    cudaFuncSetAttribute(gemm_mma<false>, cudaFuncAttributeMaxDynamicSharedMemorySize, GEMM_SMEM);
    cudaFuncSetAttribute(attn_mma, cudaFuncAttributeMaxDynamicSharedMemorySize, ATTN_SMEM);

    // Pre-round inputs to tf32 (removes all cvt from GEMM mainloops)
    round_x<<<MROWS * CDIM / 1024, 256>>>(x, x_ptr);
    transpose_k<<<dim3(QKV_N / 32, CDIM / 32), dim3(32, 8)>>>(W_qkv, wtq_ptr, CDIM, QKV_N);
    transpose_k<<<dim3(CDIM / 32, CDIM / 32), dim3(32, 8)>>>(W_o, wto_ptr, CDIM, CDIM);

    // qkv = tf32_round(x @ W_qkv + b_qkv)   [4096, 3072]
    gemm_mma<true><<<dim3(QKV_N / BN, MROWS / BM), 256, GEMM_SMEM>>>(
        x_ptr, wtq_ptr, b_qkv, qkv_ptr, MROWS, QKV_N, CDIM);

    // y = attention(qkv)  (output tf32-rounded)
    attn_mma<<<dim3(TSEQ / AQ, NHEAD, BATCH), 256, ATTN_SMEM>>>(qkv_ptr, y_ptr);

    // out = y @ W_o + b_o       [4096, 1024]
    gemm_mma<false><<<dim3(CDIM / BN, MROWS / BM), 256, GEMM_SMEM>>>(
        y_ptr, wto_ptr, b_o, out, MROWS, CDIM, CDIM);
}

// round 6
// speedup vs baseline: 5.2254x; 1.0591x over previous
#include <cuda_runtime.h>
#include <math.h>
#include <cstdint>

#define BATCH 2
#define TSEQ  2048
#define CDIM  1024
#define NHEAD 16
#define HDIM  64
#define MROWS (BATCH*TSEQ)          // 4096
#define QKV_N (3*CDIM)              // 3072

// Scratch (no runtime allocation allowed)
__device__ float g_qkv[MROWS * QKV_N];     // [B*T, 3C]  (tf32-rounded)
__device__ float g_y  [MROWS * CDIM];      // [B*T, C]   (tf32-rounded)
__device__ float g_x  [MROWS * CDIM];      // tf32-rounded copy of x
__device__ float g_wt_qkv[QKV_N * CDIM];   // W_qkv^T  (tf32-rounded)
__device__ float g_wt_o  [CDIM * CDIM];    // W_o^T    (tf32-rounded)

// ---------------------------------------------------------------------------
// helpers
// ---------------------------------------------------------------------------
__device__ __forceinline__ uint32_t smem_u32(const void* p) {
    uint32_t a;
    asm("{ .reg .u64 t; cvta.to.shared.u64 t, %1; cvt.u32.u64 %0, t; }" : "=r"(a) : "l"(p));
    return a;
}
__device__ __forceinline__ uint32_t f2tf(float f) {
    uint32_t u;
    asm("cvt.rna.tf32.f32 %0, %1;" : "=r"(u) : "f"(f));
    return u;
}
__device__ __forceinline__ float f2tf_f(float f) { return __uint_as_float(f2tf(f)); }

#define CP_ASYNC16(dst, src) \
    asm volatile("cp.async.cg.shared.global [%0], [%1], 16;" :: "r"(dst), "l"(src) : "memory")
#define CP_COMMIT() asm volatile("cp.async.commit_group;" ::: "memory")
#define CP_WAIT(n)  asm volatile("cp.async.wait_group %0;" :: "n"(n) : "memory")

__device__ __forceinline__ void mma_tf32(float* c, const uint32_t* a, const uint32_t* b) {
    asm volatile(
        "mma.sync.aligned.m16n8k8.row.col.f32.tf32.tf32.f32 "
        "{%0,%1,%2,%3}, {%4,%5,%6,%7}, {%8,%9}, {%0,%1,%2,%3};"
        : "+f"(c[0]), "+f"(c[1]), "+f"(c[2]), "+f"(c[3])
        : "r"(a[0]), "r"(a[1]), "r"(a[2]), "r"(a[3]), "r"(b[0]), "r"(b[1]));
}

// ---------------------------------------------------------------------------
// mma.sync tf32 GEMM: C[M,N] = A[M,K] @ Bt[N,K]^T + bias[N]
// Inputs pre-rounded to tf32. k-permuted fragments: all LDS are 64-bit.
// CTA 128x256, BK=32, 3-stage cp.async, 8 warps (2x4), warp tile 64x64.
// ---------------------------------------------------------------------------
#define BM 128
#define BN 256
#define BK 32
#define NST 3
#define SROW 40                                  // == 8 mod 32: conflict-free LDS.64
#define STAGE_FLTS ((BM + BN) * SROW)            // 15360
#define GEMM_SMEM  (NST * STAGE_FLTS * 4)        // 184320 bytes

template <bool ROUND>
__global__ __launch_bounds__(256, 1) void gemm_mma(
    const float* __restrict__ A, const float* __restrict__ Bt,
    const float* __restrict__ bias, float* __restrict__ C,
    int M, int N, int K)
{
    extern __shared__ float sm[];
    const uint32_t sbase = smem_u32(sm);
    const int tid  = threadIdx.x;
    const int lane = tid & 31;
    const int w    = tid >> 5;
    const int wr   = w >> 2;       // 0..1 (row of 64)
    const int wc   = w & 3;        // 0..3 (col of 64)
    const int g    = lane >> 2;
    const int la3  = lane & 3;
    const int row0 = blockIdx.y * BM;
    const int col0 = blockIdx.x * BN;

    float c[4][8][4];
    #pragma unroll
    for (int i = 0; i < 4; ++i)
        #pragma unroll
        for (int j = 0; j < 8; ++j)
            #pragma unroll
            for (int q = 0; q < 4; ++q) c[i][j][q] = 0.f;

    const int nchunk = K / BK;

    auto load_stage = [&](int s, int kt) {
        uint32_t sa = sbase + (uint32_t)(s * STAGE_FLTS) * 4u;
        uint32_t sb = sa + (uint32_t)(BM * SROW) * 4u;
        const float* Ab = A  + (size_t)row0 * K + kt * BK;
        const float* Bb = Bt + (size_t)col0 * K + kt * BK;
        #pragma unroll
        for (int it = 0; it < 4; ++it) {             // A: 128 rows x 8 chunks
            int idx = it * 256 + tid;
            int r   = idx >> 3;
            int c4  = (idx & 7) * 4;
            CP_ASYNC16(sa + (uint32_t)(r * SROW + c4) * 4u, Ab + (size_t)r * K + c4);
        }
        #pragma unroll
        for (int it = 0; it < 8; ++it) {             // B: 256 rows x 8 chunks
            int idx = it * 256 + tid;
            int r   = idx >> 3;
            int c4  = (idx & 7) * 4;
            CP_ASYNC16(sb + (uint32_t)(r * SROW + c4) * 4u, Bb + (size_t)r * K + c4);
        }
    };

    load_stage(0, 0); CP_COMMIT();
    load_stage(1, 1); CP_COMMIT();

    for (int kt = 0; kt < nchunk; ++kt) {
        CP_WAIT(1);
        __syncthreads();
        if (kt + 2 < nchunk) load_stage((kt + 2) % NST, kt + 2);
        CP_COMMIT();

        const float* sa = sm + (kt % NST) * STAGE_FLTS;
        const float* sb = sa + BM * SROW;
        #pragma unroll
        for (int ks = 0; ks < 4; ++ks) {
            const int kb = ks * 8 + 2 * la3;     // k-permuted pair base
            uint32_t af[4][4], bf[8][2];
            #pragma unroll
            for (int mt = 0; mt < 4; ++mt) {
                int r0 = wr * 64 + mt * 16 + g;
                float2 a02 = *(const float2*)&sa[r0 * SROW + kb];
                float2 a13 = *(const float2*)&sa[(r0 + 8) * SROW + kb];
                af[mt][0] = __float_as_uint(a02.x);
                af[mt][2] = __float_as_uint(a02.y);
                af[mt][1] = __float_as_uint(a13.x);
                af[mt][3] = __float_as_uint(a13.y);
            }
            #pragma unroll
            for (int nt = 0; nt < 8; ++nt) {
                int n0 = wc * 64 + nt * 8 + g;
                float2 b01 = *(const float2*)&sb[n0 * SROW + kb];
                bf[nt][0] = __float_as_uint(b01.x);
                bf[nt][1] = __float_as_uint(b01.y);
            }
            #pragma unroll
            for (int mt = 0; mt < 4; ++mt)
                #pragma unroll
                for (int nt = 0; nt < 8; ++nt)
                    mma_tf32(c[mt][nt], af[mt], bf[nt]);
        }
    }

    #pragma unroll
    for (int mt = 0; mt < 4; ++mt) {
        #pragma unroll
        for (int nt = 0; nt < 8; ++nt) {
            int r   = row0 + wr * 64 + mt * 16 + g;
            int col = col0 + wc * 64 + nt * 8 + la3 * 2;
            float2 bv = *(const float2*)&bias[col];
            float v00 = c[mt][nt][0] + bv.x, v01 = c[mt][nt][1] + bv.y;
            float v10 = c[mt][nt][2] + bv.x, v11 = c[mt][nt][3] + bv.y;
            if (ROUND) {
                v00 = f2tf_f(v00); v01 = f2tf_f(v01);
                v10 = f2tf_f(v10); v11 = f2tf_f(v11);
            }
            *(float2*)&C[(size_t)r * N + col]       = make_float2(v00, v01);
            *(float2*)&C[(size_t)(r + 8) * N + col] = make_float2(v10, v11);
        }
    }
}

// ---------------------------------------------------------------------------
// Weight transpose + tf32 round
// ---------------------------------------------------------------------------
__global__ __launch_bounds__(256) void transpose_k(
    const float* __restrict__ in, float* __restrict__ out, int R, int Ccols)
{
    __shared__ float t[32][33];
    int r0 = blockIdx.y * 32, c0 = blockIdx.x * 32;
    #pragma unroll
    for (int i = threadIdx.y; i < 32; i += 8)
        t[i][threadIdx.x] = in[(size_t)(r0 + i) * Ccols + c0 + threadIdx.x];
    __syncthreads();
    #pragma unroll
    for (int i = threadIdx.y; i < 32; i += 8)
        out[(size_t)(c0 + i) * R + r0 + threadIdx.x] = f2tf_f(t[threadIdx.x][i]);
}

__global__ __launch_bounds__(256) void round_x(
    const float* __restrict__ in, float* __restrict__ out)
{
    int i = (blockIdx.x * 256 + threadIdx.x) * 4;
    float4 v = *(const float4*)&in[i];
    v.x = f2tf_f(v.x); v.y = f2tf_f(v.y); v.z = f2tf_f(v.z); v.w = f2tf_f(v.w);
    *(float4*)&out[i] = v;
}

// ---------------------------------------------------------------------------
// Flash attention (causal), mma.sync tf32, k-permuted fragments.
// 128 queries x (b,h); 8 warps x 16 rows; KV tiles of 64, double-buffered.
// VT (transposed V) single-buffered, ALIASED into dead Q staging region:
//  - qf registers filled before first mainloop barrier
//  - PV reads of tile t complete before iter t+1 entry barrier, which
//    precedes iter t+1 transpose writes
// Smem 108.5KB -> 2 CTAs/SM. P merged into S registers (layout permute).
// ---------------------------------------------------------------------------
#define AQ 128
#define AKV 64
#define ASTR 72                                 // == 8 mod 32: conflict-free LDS.64
#define VSTG 68                                 // == 4 mod 32: conflict-free LDS.128
#define SM_QS 0
#define SM_VT 0                                 // alias: VT reuses Q staging
#define SM_KS (AQ * ASTR)                       // 9216
#define SM_VST (SM_KS + 2 * AKV * ASTR)         // 18432
#define ATTN_SMEM ((SM_VST + 2 * AKV * VSTG) * 4)   // 108544 bytes

__global__ __launch_bounds__(256, 2) void attn_mma(
    const float* __restrict__ qkv, float* __restrict__ y)
{
    extern __shared__ float sm[];
    const uint32_t sb = smem_u32(sm);
    const int tid  = threadIdx.x;
    const int lane = tid & 31;
    const int w    = tid >> 5;
    const int g    = lane >> 2;
    const int la3  = lane & 3;

    const int qblk = (gridDim.x - 1) - blockIdx.x;   // heavy blocks first
    const int q0   = qblk * AQ;
    const int h    = blockIdx.y;
    const int b    = blockIdx.z;
    const size_t base = (size_t)b * TSEQ * QKV_N + h * HDIM;

    // Load Q tile (scaled by 1/8, exact on tf32 values)
    for (int i = tid; i < AQ * 16; i += 256) {
        int r = i >> 4, c = (i & 15) * 4;
        float4 v = *(const float4*)&qkv[base + (size_t)(q0 + r) * QKV_N + c];
        v.x *= 0.125f; v.y *= 0.125f; v.z *= 0.125f; v.w *= 0.125f;
        *(float4*)&sm[SM_QS + r * ASTR + c] = v;
    }

    const int ntile = q0 / AKV + 2;

    auto load_kv = [&](int t, int stage) {
        uint32_t ks_ = sb + (uint32_t)(SM_KS + stage * AKV * ASTR) * 4u;
        uint32_t vs_ = sb + (uint32_t)(SM_VST + stage * AKV * VSTG) * 4u;
        const float* Kg = qkv + base + CDIM     + (size_t)t * AKV * QKV_N;
        const float* Vg = qkv + base + 2 * CDIM + (size_t)t * AKV * QKV_N;
        #pragma unroll
        for (int it = 0; it < 4; ++it) {
            int idx = it * 256 + tid;
            int r = idx >> 4;               // key 0..63
            int c = (idx & 15) * 4;
            CP_ASYNC16(ks_ + (uint32_t)(r * ASTR + c) * 4u, Kg + (size_t)r * QKV_N + c);
            CP_ASYNC16(vs_ + (uint32_t)(r * VSTG + c) * 4u, Vg + (size_t)r * QKV_N + c);
        }
    };

    load_kv(0, 0); CP_COMMIT();
    __syncthreads();    // Qs visible

    // Q fragments (k-permuted): float2 loads, persistent in registers.
    // These complete before the iter-0 entry barrier -> QS is then dead.
    uint32_t qf[8][4];
    const int rl1 = w * 16 + g;
    #pragma unroll
    for (int ks = 0; ks < 8; ++ks) {
        float2 q02 = *(const float2*)&sm[SM_QS + rl1 * ASTR + ks * 8 + 2 * la3];
        float2 q13 = *(const float2*)&sm[SM_QS + (rl1 + 8) * ASTR + ks * 8 + 2 * la3];
        qf[ks][0] = __float_as_uint(q02.x);
        qf[ks][2] = __float_as_uint(q02.y);
        qf[ks][1] = __float_as_uint(q13.x);
        qf[ks][3] = __float_as_uint(q13.y);
    }

    float o[8][4];
    #pragma unroll
    for (int nt = 0; nt < 8; ++nt)
        #pragma unroll
        for (int q = 0; q < 4; ++q) o[nt][q] = 0.f;
    float m0 = -1e30f, m1 = -1e30f, l0 = 0.f, l1 = 0.f;

    const int row1 = q0 + rl1;
    const int row2 = row1 + 8;

    for (int t = 0; t < ntile; ++t) {
        if (t + 1 < ntile) load_kv(t + 1, (t + 1) & 1);
        CP_COMMIT();
        CP_WAIT(1);
        __syncthreads();   // KV(t) ready; prior PV reads of VT complete

        const int par = t & 1;
        const float* Ks_  = &sm[SM_KS  + par * AKV * ASTR];
        const float* Vst_ = &sm[SM_VST + par * AKV * VSTG];
        float*       Vt_  = &sm[SM_VT];

        // Transpose V stage -> VT [dim][key] (visible after next sync)
        #pragma unroll
        for (int it = 0; it < 4; ++it) {
            int idx = it * 256 + tid;
            int key = idx & 63;
            int c4  = (idx >> 6) * 4;
            float4 v = *(const float4*)&Vst_[key * VSTG + c4];
            Vt_[(c4 + 0) * ASTR + key] = v.x;
            Vt_[(c4 + 1) * ASTR + key] = v.y;
            Vt_[(c4 + 2) * ASTR + key] = v.z;
            Vt_[(c4 + 3) * ASTR + key] = v.w;
        }

        // S = Q K^T
        float s[8][4];
        #pragma unroll
        for (int nt = 0; nt < 8; ++nt)
            #pragma unroll
            for (int q = 0; q < 4; ++q) s[nt][q] = 0.f;
        #pragma unroll
        for (int ks = 0; ks < 8; ++ks) {
            #pragma unroll
            for (int nt = 0; nt < 8; ++nt) {
                float2 kk = *(const float2*)&Ks_[(nt * 8 + g) * ASTR + ks * 8 + 2 * la3];
                uint32_t bf[2] = { __float_as_uint(kk.x), __float_as_uint(kk.y) };
                mma_tf32(s[nt], qf[ks], bf);
            }
        }

        const int j0 = t * AKV;
        if (j0 >= q0) {   // diagonal region: causal mask
            #pragma unroll
            for (int nt = 0; nt < 8; ++nt) {
                int col = j0 + nt * 8 + 2 * la3;
                if (col     > row1) s[nt][0] = -1e30f;
                if (col + 1 > row1) s[nt][1] = -1e30f;
                if (col     > row2) s[nt][2] = -1e30f;
                if (col + 1 > row2) s[nt][3] = -1e30f;
            }
        }

        // row max
        float mx0 = -1e30f, mx1 = -1e30f;
        #pragma unroll
        for (int nt = 0; nt < 8; ++nt) {
            mx0 = fmaxf(mx0, fmaxf(s[nt][0], s[nt][1]));
            mx1 = fmaxf(mx1, fmaxf(s[nt][2], s[nt][3]));
        }
        mx0 = fmaxf(mx0, __shfl_xor_sync(0xffffffffu, mx0, 1));
        mx0 = fmaxf(mx0, __shfl_xor_sync(0xffffffffu, mx0, 2));
        mx1 = fmaxf(mx1, __shfl_xor_sync(0xffffffffu, mx1, 1));
        mx1 = fmaxf(mx1, __shfl_xor_sync(0xffffffffu, mx1, 2));

        float M0 = fmaxf(m0, mx0), M1 = fmaxf(m1, mx1);
        float corr0 = __expf(m0 - M0), corr1 = __expf(m1 - M1);
        m0 = M0; m1 = M1;

        #pragma unroll
        for (int nt = 0; nt < 8; ++nt) {
            o[nt][0] *= corr0; o[nt][1] *= corr0;
            o[nt][2] *= corr1; o[nt][3] *= corr1;
        }

        // P = exp(S - M) (tf32) IN-PLACE in s, permuted to PV A-frag layout
        float ps0 = 0.f, ps1 = 0.f;
        #pragma unroll
        for (int ks = 0; ks < 8; ++ks) {
            float p0 = f2tf_f(__expf(s[ks][0] - M0));
            float p1 = f2tf_f(__expf(s[ks][1] - M0));
            float p2 = f2tf_f(__expf(s[ks][2] - M1));
            float p3 = f2tf_f(__expf(s[ks][3] - M1));
            ps0 += p0 + p1;
            ps1 += p2 + p3;
            s[ks][0] = p0;      // (row g,   k=2*la3)
            s[ks][1] = p2;      // (row g+8, k=2*la3)
            s[ks][2] = p1;      // (row g,   k=2*la3+1)
            s[ks][3] = p3;      // (row g+8, k=2*la3+1)
        }

        ps0 += __shfl_xor_sync(0xffffffffu, ps0, 1);
        ps0 += __shfl_xor_sync(0xffffffffu, ps0, 2);
        ps1 += __shfl_xor_sync(0xffffffffu, ps1, 1);
        ps1 += __shfl_xor_sync(0xffffffffu, ps1, 2);
        l0 = l0 * corr0 + ps0;
        l1 = l1 * corr1 + ps1;

        __syncthreads();   // VT complete; all warps past K reads

        // O += P V
        #pragma unroll
        for (int ks = 0; ks < 8; ++ks) {
            #pragma unroll
            for (int nt = 0; nt < 8; ++nt) {
                float2 vv = *(const float2*)&Vt_[(nt * 8 + g) * ASTR + ks * 8 + 2 * la3];
                uint32_t bf[2] = { __float_as_uint(vv.x), __float_as_uint(vv.y) };
                mma_tf32(o[nt], (const uint32_t*)s[ks], bf);
            }
        }
    }

    const float inv0 = 1.f / l0, inv1 = 1.f / l1;
    float* y1 = &y[((size_t)b * TSEQ + row1) * CDIM + h * HDIM];
    float* y2 = &y[((size_t)b * TSEQ + row2) * CDIM + h * HDIM];
    #pragma unroll
    for (int nt = 0; nt < 8; ++nt) {
        int col = nt * 8 + 2 * la3;
        *(float2*)&y1[col] = make_float2(f2tf_f(o[nt][0] * inv0), f2tf_f(o[nt][1] * inv0));
        *(float2*)&y2[col] = make_float2(f2tf_f(o[nt][2] * inv1), f2tf_f(o[nt][3] * inv1));
    }
}

// ---------------------------------------------------------------------------
extern "C" void kernel_launch(void* const* d_in, const int* in_sizes, int n_in,
                              void* d_out, int out_size)
{
    const float* x     = (const float*)d_in[0];
    const float* W_qkv = (const float*)d_in[1];
    const float* b_qkv = (const float*)d_in[2];
    const float* W_o   = (const float*)d_in[3];
    const float* b_o   = (const float*)d_in[4];
    float* out = (float*)d_out;

    float *qkv_ptr, *y_ptr, *x_ptr, *wtq_ptr, *wto_ptr;
    cudaGetSymbolAddress((void**)&qkv_ptr, g_qkv);
    cudaGetSymbolAddress((void**)&y_ptr,   g_y);
    cudaGetSymbolAddress((void**)&x_ptr,   g_x);
    cudaGetSymbolAddress((void**)&wtq_ptr, g_wt_qkv);
    cudaGetSymbolAddress((void**)&wto_ptr, g_wt_o);

    cudaFuncSetAttribute(gemm_mma<true>,  cudaFuncAttributeMaxDynamicSharedMemorySize, GEMM_SMEM);
    cudaFuncSetAttribute(gemm_mma<false>, cudaFuncAttributeMaxDynamicSharedMemorySize, GEMM_SMEM);
    cudaFuncSetAttribute(attn_mma, cudaFuncAttributeMaxDynamicSharedMemorySize, ATTN_SMEM);

    // Pre-round inputs to tf32
    round_x<<<MROWS * CDIM / 1024, 256>>>(x, x_ptr);
    transpose_k<<<dim3(QKV_N / 32, CDIM / 32), dim3(32, 8)>>>(W_qkv, wtq_ptr, CDIM, QKV_N);
    transpose_k<<<dim3(CDIM / 32, CDIM / 32), dim3(32, 8)>>>(W_o, wto_ptr, CDIM, CDIM);

    // qkv = tf32_round(x @ W_qkv + b_qkv)   [4096, 3072]
    gemm_mma<true><<<dim3(QKV_N / BN, MROWS / BM), 256, GEMM_SMEM>>>(
        x_ptr, wtq_ptr, b_qkv, qkv_ptr, MROWS, QKV_N, CDIM);

    // y = attention(qkv)
    attn_mma<<<dim3(TSEQ / AQ, NHEAD, BATCH), 256, ATTN_SMEM>>>(qkv_ptr, y_ptr);

    // out = y @ W_o + b_o       [4096, 1024]
    gemm_mma<false><<<dim3(CDIM / BN, MROWS / BM), 256, GEMM_SMEM>>>(
        y_ptr, wto_ptr, b_o, out, MROWS, CDIM, CDIM);
}